// round 13
// baseline (speedup 1.0000x reference)
#include <cuda_runtime.h>
#include <cuda_fp16.h>
#include <cstdint>

#define N_NODES 100000
#define IN_DIM  256
#define OUT_DIM 128
#define CAP     128              // slots per node (mean deg 32, P(>128) ~ e^-80)
#define CAP_SH  7

// ---------------- static scratch (no allocations allowed) -------------------
__device__ __half g_h[(size_t)N_NODES * OUT_DIM];       // 25.6 MB: h = X @ W (fp16)
__device__ int    g_cursor[N_NODES];                    // per-node fill cursor = degree
__device__ int2   g_edge[(size_t)N_NODES << CAP_SH];    // 102.4 MB bucketed (src,val)

// ---------------------------------------------------------------------------
__global__ void zero_cursor_kernel() {
    int i = blockIdx.x * blockDim.x + threadIdx.x;
    if (i < N_NODES) g_cursor[i] = 0;
}

// ---------------------------------------------------------------------------
// fill: 4 edges per thread, direct bucket placement (no hist/scan needed)
// ---------------------------------------------------------------------------
__global__ void fill_direct_kernel(const int* __restrict__ src, const int* __restrict__ dst,
                                   const float* __restrict__ vals, int E) {
    int q = blockIdx.x * blockDim.x + threadIdx.x;      // quad index
    int e = q * 4;
    if (e + 3 < E) {
        int4   s4 = __ldg((const int4*)(src + e));
        int4   d4 = __ldg((const int4*)(dst + e));
        float4 v4 = __ldg((const float4*)(vals + e));
        int p;
        p = atomicAdd(&g_cursor[d4.x], 1); if (p < CAP) g_edge[((size_t)d4.x << CAP_SH) + p] = make_int2(s4.x, __float_as_int(v4.x));
        p = atomicAdd(&g_cursor[d4.y], 1); if (p < CAP) g_edge[((size_t)d4.y << CAP_SH) + p] = make_int2(s4.y, __float_as_int(v4.y));
        p = atomicAdd(&g_cursor[d4.z], 1); if (p < CAP) g_edge[((size_t)d4.z << CAP_SH) + p] = make_int2(s4.z, __float_as_int(v4.z));
        p = atomicAdd(&g_cursor[d4.w], 1); if (p < CAP) g_edge[((size_t)d4.w << CAP_SH) + p] = make_int2(s4.w, __float_as_int(v4.w));
    } else {
        for (; e < E; e++) {
            int d = __ldg(dst + e);
            int p = atomicAdd(&g_cursor[d], 1);
            if (p < CAP) g_edge[((size_t)d << CAP_SH) + p] = make_int2(__ldg(src + e), __float_as_int(__ldg(vals + e)));
        }
    }
}

// ---------------------------------------------------------------------------
// tf32 tensor-core GEMM with register-prefetch pipelining.
// g_h = A[100000,256] @ B[256,128], fp16 output.
// ---------------------------------------------------------------------------
__device__ __forceinline__ uint32_t f2tf32(float f) {
    uint32_t r;
    asm("cvt.rna.tf32.f32 %0, %1;" : "=r"(r) : "f"(f));
    return r;
}

__device__ __forceinline__ void mma_tf32(float* c, const uint32_t* a, uint32_t b0, uint32_t b1) {
    asm volatile("mma.sync.aligned.m16n8k8.row.col.f32.tf32.tf32.f32 "
                 "{%0,%1,%2,%3}, {%4,%5,%6,%7}, {%8,%9}, {%0,%1,%2,%3};"
                 : "+f"(c[0]), "+f"(c[1]), "+f"(c[2]), "+f"(c[3])
                 : "r"(a[0]), "r"(a[1]), "r"(a[2]), "r"(a[3]), "r"(b0), "r"(b1));
}

#define SA 36
#define SB 136

__global__ void __launch_bounds__(256) gemm_tc_kernel(const float* __restrict__ A,
                                                      const float* __restrict__ B) {
    __shared__ uint32_t As[128 * SA];
    __shared__ uint32_t Bs[32 * SB];

    const int tid  = threadIdx.x;
    const int lane = tid & 31;
    const int warp = tid >> 5;
    const int warpM = warp & 3;
    const int warpN = warp >> 2;
    const int g = lane >> 2;
    const int t = lane & 3;
    const int blockRow = blockIdx.x * 128;

    // staging geometry (per thread: 4 float4 of A, 4 float4 of B per chunk)
    const int a_r  = tid >> 1;                 // rows tid/2 and +128? no: idx mapping below
    float acc[2][8][4] = {};
    float4 pa[4], pb[4];

    // prefetch chunk 0
    #pragma unroll
    for (int i = 0; i < 4; i++) {
        int idx = tid + i * 256;
        int r   = idx >> 3;
        int jj  = (idx & 7) * 4;
        int grow = blockRow + r;
        pa[i] = (grow < N_NODES)
            ? *reinterpret_cast<const float4*>(A + (size_t)grow * IN_DIM + jj)
            : make_float4(0.f, 0.f, 0.f, 0.f);
        int kr  = idx >> 5;
        int nj  = (idx & 31) * 4;
        pb[i] = *reinterpret_cast<const float4*>(B + (size_t)kr * OUT_DIM + nj);
    }

    for (int k0 = 0; k0 < IN_DIM; k0 += 32) {
        // stage prefetched chunk into smem (cvt to tf32)
        #pragma unroll
        for (int i = 0; i < 4; i++) {
            int idx = tid + i * 256;
            int r   = idx >> 3;
            int jj  = (idx & 7) * 4;
            uint32_t* p = &As[r * SA + jj];
            p[0] = f2tf32(pa[i].x); p[1] = f2tf32(pa[i].y); p[2] = f2tf32(pa[i].z); p[3] = f2tf32(pa[i].w);
            int kr  = idx >> 5;
            int nj  = (idx & 31) * 4;
            uint32_t* q = &Bs[kr * SB + nj];
            q[0] = f2tf32(pb[i].x); q[1] = f2tf32(pb[i].y); q[2] = f2tf32(pb[i].z); q[3] = f2tf32(pb[i].w);
        }
        __syncthreads();

        // issue next chunk's loads BEFORE compute (latency hides under MMAs)
        if (k0 + 32 < IN_DIM) {
            #pragma unroll
            for (int i = 0; i < 4; i++) {
                int idx = tid + i * 256;
                int r   = idx >> 3;
                int jj  = (idx & 7) * 4;
                int grow = blockRow + r;
                pa[i] = (grow < N_NODES)
                    ? *reinterpret_cast<const float4*>(A + (size_t)grow * IN_DIM + k0 + 32 + jj)
                    : make_float4(0.f, 0.f, 0.f, 0.f);
                int kr  = idx >> 5;
                int nj  = (idx & 31) * 4;
                pb[i] = *reinterpret_cast<const float4*>(B + (size_t)(k0 + 32 + kr) * OUT_DIM + nj);
            }
        }

        #pragma unroll
        for (int ks = 0; ks < 4; ks++) {
            const int kk = ks * 8;
            uint32_t a[2][4];
            #pragma unroll
            for (int mi = 0; mi < 2; mi++) {
                int rb = warpM * 32 + mi * 16 + g;
                a[mi][0] = As[rb * SA + kk + t];
                a[mi][1] = As[(rb + 8) * SA + kk + t];
                a[mi][2] = As[rb * SA + kk + t + 4];
                a[mi][3] = As[(rb + 8) * SA + kk + t + 4];
            }
            #pragma unroll
            for (int ni = 0; ni < 8; ni++) {
                int nb = warpN * 64 + ni * 8 + g;
                uint32_t b0 = Bs[(kk + t) * SB + nb];
                uint32_t b1 = Bs[(kk + t + 4) * SB + nb];
                mma_tf32(acc[0][ni], a[0], b0, b1);
                mma_tf32(acc[1][ni], a[1], b0, b1);
            }
        }
        __syncthreads();
    }

    #pragma unroll
    for (int mi = 0; mi < 2; mi++) {
        int r0 = blockRow + warpM * 32 + mi * 16 + g;
        int r1 = r0 + 8;
        #pragma unroll
        for (int ni = 0; ni < 8; ni++) {
            int cb = warpN * 64 + ni * 8 + t * 2;
            if (r0 < N_NODES)
                *reinterpret_cast<__half2*>(g_h + (size_t)r0 * OUT_DIM + cb) =
                    __floats2half2_rn(acc[mi][ni][0], acc[mi][ni][1]);
            if (r1 < N_NODES)
                *reinterpret_cast<__half2*>(g_h + (size_t)r1 * OUT_DIM + cb) =
                    __floats2half2_rn(acc[mi][ni][2], acc[mi][ni][3]);
        }
    }
}

// ---------------------------------------------------------------------------
// gather: HALF-WARP per dst node, lane owns 8 fp16 cols (one LDG.128/edge).
// 4-edge unroll: 4 independent h-row loads + 2 uniform edge loads in flight.
// ---------------------------------------------------------------------------
__device__ __forceinline__ void acc_edge(float4& accA, float4& accB, uint4 q, float v) {
    float2 f;
    f = __half22float2(*reinterpret_cast<__half2*>(&q.x)); accA.x += v * f.x; accA.y += v * f.y;
    f = __half22float2(*reinterpret_cast<__half2*>(&q.y)); accA.z += v * f.x; accA.w += v * f.y;
    f = __half22float2(*reinterpret_cast<__half2*>(&q.z)); accB.x += v * f.x; accB.y += v * f.y;
    f = __half22float2(*reinterpret_cast<__half2*>(&q.w)); accB.z += v * f.x; accB.w += v * f.y;
}

__global__ void __launch_bounds__(256) gather_kernel(const float* __restrict__ b,
                                                     float* __restrict__ out) {
    int node = (blockIdx.x * blockDim.x + threadIdx.x) >> 4;
    int lane = threadIdx.x & 15;
    if (node >= N_NODES) return;

    const int c = lane * 8;
    int cnt = __ldg(&g_cursor[node]);
    if (cnt > CAP) cnt = CAP;
    const int2* ebase = &g_edge[(size_t)node << CAP_SH];

    float4 accA = *reinterpret_cast<const float4*>(b + c);
    float4 accB = *reinterpret_cast<const float4*>(b + c + 4);

    int e = 0;
    for (; e + 3 < cnt; e += 4) {
        int4 pA = __ldg(reinterpret_cast<const int4*>(ebase + e));       // edges e, e+1
        int4 pB = __ldg(reinterpret_cast<const int4*>(ebase + e + 2));   // edges e+2, e+3
        uint4 q0 = *reinterpret_cast<const uint4*>(g_h + (size_t)pA.x * OUT_DIM + c);
        uint4 q1 = *reinterpret_cast<const uint4*>(g_h + (size_t)pA.z * OUT_DIM + c);
        uint4 q2 = *reinterpret_cast<const uint4*>(g_h + (size_t)pB.x * OUT_DIM + c);
        uint4 q3 = *reinterpret_cast<const uint4*>(g_h + (size_t)pB.z * OUT_DIM + c);
        acc_edge(accA, accB, q0, __int_as_float(pA.y));
        acc_edge(accA, accB, q1, __int_as_float(pA.w));
        acc_edge(accA, accB, q2, __int_as_float(pB.y));
        acc_edge(accA, accB, q3, __int_as_float(pB.w));
    }
    if (e + 1 < cnt) {
        int4 pA = __ldg(reinterpret_cast<const int4*>(ebase + e));
        uint4 q0 = *reinterpret_cast<const uint4*>(g_h + (size_t)pA.x * OUT_DIM + c);
        uint4 q1 = *reinterpret_cast<const uint4*>(g_h + (size_t)pA.z * OUT_DIM + c);
        acc_edge(accA, accB, q0, __int_as_float(pA.y));
        acc_edge(accA, accB, q1, __int_as_float(pA.w));
        e += 2;
    }
    if (e < cnt) {
        int2 p0 = __ldg(ebase + e);
        uint4 q0 = *reinterpret_cast<const uint4*>(g_h + (size_t)p0.x * OUT_DIM + c);
        acc_edge(accA, accB, q0, __int_as_float(p0.y));
    }

    float* o = out + (size_t)node * OUT_DIM + c;
    *reinterpret_cast<float4*>(o)     = accA;
    *reinterpret_cast<float4*>(o + 4) = accB;
}

// ---------------------------------------------------------------------------
extern "C" void kernel_launch(void* const* d_in, const int* in_sizes, int n_in,
                              void* d_out, int out_size) {
    const float* feature_map = (const float*)d_in[0];
    const int*   edge_src    = (const int*)d_in[1];
    const int*   edge_dst    = (const int*)d_in[2];
    const float* edge_vals   = (const float*)d_in[3];
    const float* weights     = (const float*)d_in[4];
    const float* bias        = (const float*)d_in[5];
    float*       out         = (float*)d_out;

    const int E = in_sizes[1];

    // Fork a side stream so the GEMM overlaps the bucket build.
    cudaStream_t s2;
    cudaStreamCreate(&s2);
    cudaEvent_t ev_fork, ev_gemm;
    cudaEventCreateWithFlags(&ev_fork, cudaEventDisableTiming);
    cudaEventCreateWithFlags(&ev_gemm, cudaEventDisableTiming);

    cudaEventRecord(ev_fork, 0);
    cudaStreamWaitEvent(s2, ev_fork, 0);

    // side stream: h = X @ W
    gemm_tc_kernel<<<(N_NODES + 127) / 128, 256, 0, s2>>>(feature_map, weights);
    cudaEventRecord(ev_gemm, s2);

    // main stream: bucket build (no hist/scan)
    zero_cursor_kernel<<<(N_NODES + 255) / 256, 256>>>();
    {
        int quads = (E + 3) / 4;
        fill_direct_kernel<<<(quads + 255) / 256, 256>>>(edge_src, edge_dst, edge_vals, E);
    }

    // join: gather needs both buckets and g_h
    cudaStreamWaitEvent(0, ev_gemm, 0);
    {
        long long threads = (long long)N_NODES * 16;
        int blocks = (int)((threads + 255) / 256);
        gather_kernel<<<blocks, 256>>>(bias, out);
    }

    cudaEventDestroy(ev_fork);
    cudaEventDestroy(ev_gemm);
    cudaStreamDestroy(s2);
}

// round 14
// speedup vs baseline: 1.2007x; 1.2007x over previous
#include <cuda_runtime.h>
#include <cuda_fp16.h>
#include <cstdint>

#define N_NODES 100000
#define IN_DIM  256
#define OUT_DIM 128
#define CAP     128              // slots per node (mean deg 32, P(>128) ~ e^-80)
#define CAP_SH  7

// ---------------- static scratch (no allocations allowed) -------------------
__device__ __half g_h[(size_t)N_NODES * OUT_DIM];       // 25.6 MB: h = X @ W (fp16)
__device__ int    g_cursor[N_NODES];                    // per-node fill cursor = degree
__device__ int2   g_edge[(size_t)N_NODES << CAP_SH];    // 102.4 MB bucketed (src,val)

// ---------------------------------------------------------------------------
__global__ void zero_cursor_kernel() {
    int i = blockIdx.x * blockDim.x + threadIdx.x;
    if (i < N_NODES) g_cursor[i] = 0;
}

// ---------------------------------------------------------------------------
// fill: 4 edges per thread, direct bucket placement (no hist/scan needed)
// ---------------------------------------------------------------------------
__global__ void fill_direct_kernel(const int* __restrict__ src, const int* __restrict__ dst,
                                   const float* __restrict__ vals, int E) {
    int q = blockIdx.x * blockDim.x + threadIdx.x;      // quad index
    int e = q * 4;
    if (e + 3 < E) {
        int4   s4 = __ldg((const int4*)(src + e));
        int4   d4 = __ldg((const int4*)(dst + e));
        float4 v4 = __ldg((const float4*)(vals + e));
        int p;
        p = atomicAdd(&g_cursor[d4.x], 1); if (p < CAP) g_edge[((size_t)d4.x << CAP_SH) + p] = make_int2(s4.x, __float_as_int(v4.x));
        p = atomicAdd(&g_cursor[d4.y], 1); if (p < CAP) g_edge[((size_t)d4.y << CAP_SH) + p] = make_int2(s4.y, __float_as_int(v4.y));
        p = atomicAdd(&g_cursor[d4.z], 1); if (p < CAP) g_edge[((size_t)d4.z << CAP_SH) + p] = make_int2(s4.z, __float_as_int(v4.z));
        p = atomicAdd(&g_cursor[d4.w], 1); if (p < CAP) g_edge[((size_t)d4.w << CAP_SH) + p] = make_int2(s4.w, __float_as_int(v4.w));
    } else {
        for (; e < E; e++) {
            int d = __ldg(dst + e);
            int p = atomicAdd(&g_cursor[d], 1);
            if (p < CAP) g_edge[((size_t)d << CAP_SH) + p] = make_int2(__ldg(src + e), __float_as_int(__ldg(vals + e)));
        }
    }
}

// ---------------------------------------------------------------------------
// tf32 tensor-core GEMM (R12 form — no register prefetch).
// g_h = A[100000,256] @ B[256,128], fp16 output.
// ---------------------------------------------------------------------------
__device__ __forceinline__ uint32_t f2tf32(float f) {
    uint32_t r;
    asm("cvt.rna.tf32.f32 %0, %1;" : "=r"(r) : "f"(f));
    return r;
}

__device__ __forceinline__ void mma_tf32(float* c, const uint32_t* a, uint32_t b0, uint32_t b1) {
    asm volatile("mma.sync.aligned.m16n8k8.row.col.f32.tf32.tf32.f32 "
                 "{%0,%1,%2,%3}, {%4,%5,%6,%7}, {%8,%9}, {%0,%1,%2,%3};"
                 : "+f"(c[0]), "+f"(c[1]), "+f"(c[2]), "+f"(c[3])
                 : "r"(a[0]), "r"(a[1]), "r"(a[2]), "r"(a[3]), "r"(b0), "r"(b1));
}

#define SA 36
#define SB 136

__global__ void __launch_bounds__(256) gemm_tc_kernel(const float* __restrict__ A,
                                                      const float* __restrict__ B) {
    __shared__ uint32_t As[128 * SA];
    __shared__ uint32_t Bs[32 * SB];

    const int tid  = threadIdx.x;
    const int lane = tid & 31;
    const int warp = tid >> 5;
    const int warpM = warp & 3;
    const int warpN = warp >> 2;
    const int g = lane >> 2;
    const int t = lane & 3;
    const int blockRow = blockIdx.x * 128;

    float acc[2][8][4] = {};

    for (int k0 = 0; k0 < IN_DIM; k0 += 32) {
        #pragma unroll
        for (int i = 0; i < 4; i++) {
            int idx = tid + i * 256;
            int r   = idx >> 3;
            int jj  = (idx & 7) * 4;
            int grow = blockRow + r;
            float4 v = (grow < N_NODES)
                ? *reinterpret_cast<const float4*>(A + (size_t)grow * IN_DIM + k0 + jj)
                : make_float4(0.f, 0.f, 0.f, 0.f);
            uint32_t* p = &As[r * SA + jj];
            p[0] = f2tf32(v.x); p[1] = f2tf32(v.y); p[2] = f2tf32(v.z); p[3] = f2tf32(v.w);
        }
        #pragma unroll
        for (int i = 0; i < 4; i++) {
            int idx = tid + i * 256;
            int kr  = idx >> 5;
            int nj  = (idx & 31) * 4;
            float4 v = *reinterpret_cast<const float4*>(B + (size_t)(k0 + kr) * OUT_DIM + nj);
            uint32_t* p = &Bs[kr * SB + nj];
            p[0] = f2tf32(v.x); p[1] = f2tf32(v.y); p[2] = f2tf32(v.z); p[3] = f2tf32(v.w);
        }
        __syncthreads();

        #pragma unroll
        for (int ks = 0; ks < 4; ks++) {
            const int kk = ks * 8;
            uint32_t a[2][4];
            #pragma unroll
            for (int mi = 0; mi < 2; mi++) {
                int rb = warpM * 32 + mi * 16 + g;
                a[mi][0] = As[rb * SA + kk + t];
                a[mi][1] = As[(rb + 8) * SA + kk + t];
                a[mi][2] = As[rb * SA + kk + t + 4];
                a[mi][3] = As[(rb + 8) * SA + kk + t + 4];
            }
            #pragma unroll
            for (int ni = 0; ni < 8; ni++) {
                int nb = warpN * 64 + ni * 8 + g;
                uint32_t b0 = Bs[(kk + t) * SB + nb];
                uint32_t b1 = Bs[(kk + t + 4) * SB + nb];
                mma_tf32(acc[0][ni], a[0], b0, b1);
                mma_tf32(acc[1][ni], a[1], b0, b1);
            }
        }
        __syncthreads();
    }

    #pragma unroll
    for (int mi = 0; mi < 2; mi++) {
        int r0 = blockRow + warpM * 32 + mi * 16 + g;
        int r1 = r0 + 8;
        #pragma unroll
        for (int ni = 0; ni < 8; ni++) {
            int cb = warpN * 64 + ni * 8 + t * 2;
            if (r0 < N_NODES)
                *reinterpret_cast<__half2*>(g_h + (size_t)r0 * OUT_DIM + cb) =
                    __floats2half2_rn(acc[mi][ni][0], acc[mi][ni][1]);
            if (r1 < N_NODES)
                *reinterpret_cast<__half2*>(g_h + (size_t)r1 * OUT_DIM + cb) =
                    __floats2half2_rn(acc[mi][ni][2], acc[mi][ni][3]);
        }
    }
}

// ---------------------------------------------------------------------------
// gather: HALF-WARP per dst node, lane owns 8 fp16 cols (one LDG.128/edge).
// 2-edge body (R12 form) + software-pipelined edge-payload prefetch:
// next iteration's int4 edge load is issued before this iteration's h loads,
// breaking the edge-load -> h-load serial chain.
// ---------------------------------------------------------------------------
__device__ __forceinline__ void acc_edge(float4& accA, float4& accB, uint4 q, float v) {
    float2 f;
    f = __half22float2(*reinterpret_cast<__half2*>(&q.x)); accA.x += v * f.x; accA.y += v * f.y;
    f = __half22float2(*reinterpret_cast<__half2*>(&q.y)); accA.z += v * f.x; accA.w += v * f.y;
    f = __half22float2(*reinterpret_cast<__half2*>(&q.z)); accB.x += v * f.x; accB.y += v * f.y;
    f = __half22float2(*reinterpret_cast<__half2*>(&q.w)); accB.z += v * f.x; accB.w += v * f.y;
}

__global__ void __launch_bounds__(256) gather_kernel(const float* __restrict__ b,
                                                     float* __restrict__ out) {
    int node = (blockIdx.x * blockDim.x + threadIdx.x) >> 4;
    int lane = threadIdx.x & 15;
    if (node >= N_NODES) return;

    const int c = lane * 8;
    int cnt = __ldg(&g_cursor[node]);
    if (cnt > CAP) cnt = CAP;
    const int2* ebase = &g_edge[(size_t)node << CAP_SH];

    float4 accA = *reinterpret_cast<const float4*>(b + c);
    float4 accB = *reinterpret_cast<const float4*>(b + c + 4);

    int e = 0;
    if (e + 1 < cnt) {
        int4 pp = __ldg(reinterpret_cast<const int4*>(ebase + e));       // prime
        for (; e + 1 < cnt; e += 2) {
            // prefetch next pair before consuming current one
            int4 nxt;
            if (e + 3 < cnt) nxt = __ldg(reinterpret_cast<const int4*>(ebase + e + 2));
            uint4 q0 = *reinterpret_cast<const uint4*>(g_h + (size_t)pp.x * OUT_DIM + c);
            uint4 q1 = *reinterpret_cast<const uint4*>(g_h + (size_t)pp.z * OUT_DIM + c);
            acc_edge(accA, accB, q0, __int_as_float(pp.y));
            acc_edge(accA, accB, q1, __int_as_float(pp.w));
            pp = nxt;
        }
    }
    if (e < cnt) {
        int2 p0 = __ldg(ebase + e);
        uint4 q0 = *reinterpret_cast<const uint4*>(g_h + (size_t)p0.x * OUT_DIM + c);
        acc_edge(accA, accB, q0, __int_as_float(p0.y));
    }

    float* o = out + (size_t)node * OUT_DIM + c;
    *reinterpret_cast<float4*>(o)     = accA;
    *reinterpret_cast<float4*>(o + 4) = accB;
}

// ---------------------------------------------------------------------------
extern "C" void kernel_launch(void* const* d_in, const int* in_sizes, int n_in,
                              void* d_out, int out_size) {
    const float* feature_map = (const float*)d_in[0];
    const int*   edge_src    = (const int*)d_in[1];
    const int*   edge_dst    = (const int*)d_in[2];
    const float* edge_vals   = (const float*)d_in[3];
    const float* weights     = (const float*)d_in[4];
    const float* bias        = (const float*)d_in[5];
    float*       out         = (float*)d_out;

    const int E = in_sizes[1];

    // Fork a side stream so the GEMM overlaps the bucket build.
    cudaStream_t s2;
    cudaStreamCreate(&s2);
    cudaEvent_t ev_fork, ev_gemm;
    cudaEventCreateWithFlags(&ev_fork, cudaEventDisableTiming);
    cudaEventCreateWithFlags(&ev_gemm, cudaEventDisableTiming);

    cudaEventRecord(ev_fork, 0);
    cudaStreamWaitEvent(s2, ev_fork, 0);

    // side stream: h = X @ W
    gemm_tc_kernel<<<(N_NODES + 127) / 128, 256, 0, s2>>>(feature_map, weights);
    cudaEventRecord(ev_gemm, s2);

    // main stream: bucket build (no hist/scan)
    zero_cursor_kernel<<<(N_NODES + 255) / 256, 256>>>();
    {
        int quads = (E + 3) / 4;
        fill_direct_kernel<<<(quads + 255) / 256, 256>>>(edge_src, edge_dst, edge_vals, E);
    }

    // join: gather needs both buckets and g_h
    cudaStreamWaitEvent(0, ev_gemm, 0);
    {
        long long threads = (long long)N_NODES * 16;
        int blocks = (int)((threads + 255) / 256);
        gather_kernel<<<blocks, 256>>>(bias, out);
    }

    cudaEventDestroy(ev_fork);
    cudaEventDestroy(ev_gemm);
    cudaStreamDestroy(s2);
}